// round 1
// baseline (speedup 1.0000x reference)
#include <cuda_runtime.h>
#include <math.h>

#define BB   2
#define SS   2048
#define DMODEL 1024
#define HQ   16
#define HKV  4
#define DK   64
#define KVD  256   // HKV*DK

// ---------------- scratch (no allocations allowed) ----------------
__device__ float g_Q[BB*SS*DMODEL];      // 16 MB
__device__ float g_K[BB*SS*KVD];
__device__ float g_V[BB*SS*KVD];
__device__ float g_attn[BB*SS*DMODEL];   // 16 MB
__device__ float g_cos[SS*(DK/2)];
__device__ float g_sin[SS*(DK/2)];

// ---------------- RoPE frequency table ----------------
// Faithful to reference: theta = 1/(10000^(2j)/64).  j>=5 -> 10000^(2j)=inf -> theta=0.
// cos/sin computed in double (pair 0 has theta=64, angles up to 131008).
__global__ void freq_kernel() {
    int idx = blockIdx.x * blockDim.x + threadIdx.x;
    if (idx >= SS * (DK/2)) return;
    int s = idx / (DK/2);
    int j = idx % (DK/2);
    float p = powf(10000.0f, 2.0f * (float)j);
    float theta = 1.0f / (p / (float)DK);
    float ang = (float)s * theta;
    double a = (double)ang;
    g_cos[idx] = (float)cos(a);
    g_sin[idx] = (float)sin(a);
}

// ---------------- RoPE apply (in place on Q and K) ----------------
// Reference quirk: out1 = x1*c - x2*s ; out2 = x2*s + x1*c
__global__ void rope_kernel() {
    int idx = blockIdx.x * blockDim.x + threadIdx.x;
    const int nQ = BB*SS*HQ*(DK/2);
    const int nK = BB*SS*HKV*(DK/2);
    if (idx < nQ) {
        int pr = idx & 31;
        int t  = idx >> 5;
        int h  = t % HQ;  t /= HQ;
        int s  = t % SS;
        int b  = t / SS;
        float* p = g_Q + ((size_t)(b*SS + s))*DMODEL + h*DK + pr*2;
        float c  = g_cos[s*(DK/2) + pr];
        float sn = g_sin[s*(DK/2) + pr];
        float x1 = p[0], x2 = p[1];
        p[0] = x1*c - x2*sn;
        p[1] = x2*sn + x1*c;
    } else if (idx < nQ + nK) {
        int j  = idx - nQ;
        int pr = j & 31;
        int t  = j >> 5;
        int h  = t % HKV; t /= HKV;
        int s  = t % SS;
        int b  = t / SS;
        float* p = g_K + ((size_t)(b*SS + s))*KVD + h*DK + pr*2;
        float c  = g_cos[s*(DK/2) + pr];
        float sn = g_sin[s*(DK/2) + pr];
        float x1 = p[0], x2 = p[1];
        p[0] = x1*c - x2*sn;
        p[1] = x2*sn + x1*c;
    }
}

// ---------------- fp32 GEMM: C[M,N] = A[M,Kd] * W[N,Kd]^T + bias ----------------
// 64x64 block, Kd-tile 16, 256 threads, 4x4 micro-tile via transposed smem.
__global__ void gemm_tn(const float* __restrict__ A, const float* __restrict__ W,
                        const float* __restrict__ bias, float* __restrict__ C,
                        int M, int N, int Kd) {
    __shared__ float At[16][64];
    __shared__ float Wt[16][64];
    int tid = threadIdx.x;
    int ty = tid >> 4, tx = tid & 15;
    int rowbase = blockIdx.y * 64;
    int colbase = blockIdx.x * 64;

    float acc[4][4];
#pragma unroll
    for (int i = 0; i < 4; i++)
#pragma unroll
        for (int j = 0; j < 4; j++) acc[i][j] = 0.0f;

    int r  = tid >> 2;        // 0..63
    int k4 = tid & 3;         // 0..3  (k4*4 .. k4*4+3)

    for (int kb = 0; kb < Kd; kb += 16) {
        float4 av = *(const float4*)&A[(size_t)(rowbase + r)*Kd + kb + k4*4];
        At[k4*4+0][r] = av.x; At[k4*4+1][r] = av.y;
        At[k4*4+2][r] = av.z; At[k4*4+3][r] = av.w;
        float4 wv = *(const float4*)&W[(size_t)(colbase + r)*Kd + kb + k4*4];
        Wt[k4*4+0][r] = wv.x; Wt[k4*4+1][r] = wv.y;
        Wt[k4*4+2][r] = wv.z; Wt[k4*4+3][r] = wv.w;
        __syncthreads();
#pragma unroll
        for (int kk = 0; kk < 16; kk++) {
            float4 a = *(const float4*)&At[kk][ty*4];
            float4 b = *(const float4*)&Wt[kk][tx*4];
            acc[0][0] += a.x*b.x; acc[0][1] += a.x*b.y; acc[0][2] += a.x*b.z; acc[0][3] += a.x*b.w;
            acc[1][0] += a.y*b.x; acc[1][1] += a.y*b.y; acc[1][2] += a.y*b.z; acc[1][3] += a.y*b.w;
            acc[2][0] += a.z*b.x; acc[2][1] += a.z*b.y; acc[2][2] += a.z*b.z; acc[2][3] += a.z*b.w;
            acc[3][0] += a.w*b.x; acc[3][1] += a.w*b.y; acc[3][2] += a.w*b.z; acc[3][3] += a.w*b.w;
        }
        __syncthreads();
    }

    float b0 = bias[colbase + tx*4 + 0];
    float b1 = bias[colbase + tx*4 + 1];
    float b2 = bias[colbase + tx*4 + 2];
    float b3 = bias[colbase + tx*4 + 3];
#pragma unroll
    for (int i = 0; i < 4; i++) {
        float4 c;
        c.x = acc[i][0] + b0; c.y = acc[i][1] + b1;
        c.z = acc[i][2] + b2; c.w = acc[i][3] + b3;
        *(float4*)&C[(size_t)(rowbase + ty*4 + i)*N + colbase + tx*4] = c;
    }
}

// ---------------- flash attention (fp32, causal, GQA) ----------------
// grid: (32 qtiles, B*HQ).  64x64 tiles, online softmax.
// smem: Qt (Q^T), KP (K^T, later reused as P^T), Vs (natural) = exactly 48 KB.
__global__ void attn_kernel() {
    __shared__ float Qt[64][64];
    __shared__ float KP[64][64];
    __shared__ float Vs[64][64];

    int tid = threadIdx.x;
    int ty = tid >> 4, tx = tid & 15;
    int qt = (int)gridDim.x - 1 - (int)blockIdx.x;   // big tiles first
    int bh = blockIdx.y;
    int b = bh >> 4, h = bh & 15;
    int kvh = h >> 2;

    const float* Qbase = g_Q + (size_t)b*SS*DMODEL + h*DK;
    const float* Kbase = g_K + (size_t)b*SS*KVD + kvh*DK;
    const float* Vbase = g_V + (size_t)b*SS*KVD + kvh*DK;
    int q0 = qt * 64;

    // load Q tile transposed
#pragma unroll
    for (int i = 0; i < 4; i++) {
        int l = tid + 256*i;
        int rr = l >> 4, c4 = l & 15;
        float4 v = *(const float4*)&Qbase[(size_t)(q0 + rr)*DMODEL + c4*4];
        Qt[c4*4+0][rr] = v.x; Qt[c4*4+1][rr] = v.y;
        Qt[c4*4+2][rr] = v.z; Qt[c4*4+3][rr] = v.w;
    }

    float m[4], lsum[4], o[4][4];
#pragma unroll
    for (int i = 0; i < 4; i++) {
        m[i] = -1e30f; lsum[i] = 0.0f;
#pragma unroll
        for (int j = 0; j < 4; j++) o[i][j] = 0.0f;
    }

    const float scale = 0.125f;   // 1/sqrt(64)

    for (int kt = 0; kt <= qt; kt++) {
        int k0 = kt * 64;
        // load K (transposed) and V (natural)
#pragma unroll
        for (int i = 0; i < 4; i++) {
            int l = tid + 256*i;
            int rr = l >> 4, c4 = l & 15;
            float4 kv = *(const float4*)&Kbase[(size_t)(k0 + rr)*KVD + c4*4];
            KP[c4*4+0][rr] = kv.x; KP[c4*4+1][rr] = kv.y;
            KP[c4*4+2][rr] = kv.z; KP[c4*4+3][rr] = kv.w;
            float4 vv = *(const float4*)&Vbase[(size_t)(k0 + rr)*KVD + c4*4];
            *(float4*)&Vs[rr][c4*4] = vv;
        }
        __syncthreads();

        float s[4][4];
#pragma unroll
        for (int i = 0; i < 4; i++)
#pragma unroll
            for (int j = 0; j < 4; j++) s[i][j] = 0.0f;

#pragma unroll
        for (int d = 0; d < 64; d++) {
            float4 a  = *(const float4*)&Qt[d][ty*4];
            float4 bv = *(const float4*)&KP[d][tx*4];
            s[0][0] += a.x*bv.x; s[0][1] += a.x*bv.y; s[0][2] += a.x*bv.z; s[0][3] += a.x*bv.w;
            s[1][0] += a.y*bv.x; s[1][1] += a.y*bv.y; s[1][2] += a.y*bv.z; s[1][3] += a.y*bv.w;
            s[2][0] += a.z*bv.x; s[2][1] += a.z*bv.y; s[2][2] += a.z*bv.z; s[2][3] += a.z*bv.w;
            s[3][0] += a.w*bv.x; s[3][1] += a.w*bv.y; s[3][2] += a.w*bv.z; s[3][3] += a.w*bv.w;
        }

        // scale + causal mask (only diagonal tile needs masking)
        if (kt == qt) {
#pragma unroll
            for (int i = 0; i < 4; i++)
#pragma unroll
                for (int j = 0; j < 4; j++) {
                    s[i][j] *= scale;
                    if (tx*4 + j > ty*4 + i) s[i][j] = -1e30f;
                }
        } else {
#pragma unroll
            for (int i = 0; i < 4; i++)
#pragma unroll
                for (int j = 0; j < 4; j++) s[i][j] *= scale;
        }

        // online softmax: reduce over the 16 threads holding a row
        float mnew[4];
#pragma unroll
        for (int i = 0; i < 4; i++) {
            float mx = fmaxf(fmaxf(s[i][0], s[i][1]), fmaxf(s[i][2], s[i][3]));
#pragma unroll
            for (int off = 8; off >= 1; off >>= 1)
                mx = fmaxf(mx, __shfl_xor_sync(0xffffffffu, mx, off));
            mnew[i] = fmaxf(m[i], mx);
        }
#pragma unroll
        for (int i = 0; i < 4; i++) {
            float corr = expf(m[i] - mnew[i]);
            float sum = 0.0f;
#pragma unroll
            for (int j = 0; j < 4; j++) {
                s[i][j] = expf(s[i][j] - mnew[i]);
                sum += s[i][j];
            }
#pragma unroll
            for (int off = 8; off >= 1; off >>= 1)
                sum += __shfl_xor_sync(0xffffffffu, sum, off);
            lsum[i] = lsum[i]*corr + sum;
            m[i] = mnew[i];
#pragma unroll
            for (int j = 0; j < 4; j++) o[i][j] *= corr;
        }

        __syncthreads();   // finished reading KP as K^T
        // store P^T into KP
#pragma unroll
        for (int i = 0; i < 4; i++)
#pragma unroll
            for (int j = 0; j < 4; j++)
                KP[tx*4 + j][ty*4 + i] = s[i][j];
        __syncthreads();

        // O += P * V
#pragma unroll
        for (int k = 0; k < 64; k++) {
            float4 a  = *(const float4*)&KP[k][ty*4];
            float4 bv = *(const float4*)&Vs[k][tx*4];
            o[0][0] += a.x*bv.x; o[0][1] += a.x*bv.y; o[0][2] += a.x*bv.z; o[0][3] += a.x*bv.w;
            o[1][0] += a.y*bv.x; o[1][1] += a.y*bv.y; o[1][2] += a.y*bv.z; o[1][3] += a.y*bv.w;
            o[2][0] += a.z*bv.x; o[2][1] += a.z*bv.y; o[2][2] += a.z*bv.z; o[2][3] += a.z*bv.w;
            o[3][0] += a.w*bv.x; o[3][1] += a.w*bv.y; o[3][2] += a.w*bv.z; o[3][3] += a.w*bv.w;
        }
        __syncthreads();   // before next tile load overwrites KP/Vs
    }

    float* Obase = g_attn + (size_t)b*SS*DMODEL + h*DK;
#pragma unroll
    for (int i = 0; i < 4; i++) {
        float inv = 1.0f / lsum[i];
        float4 st;
        st.x = o[i][0]*inv; st.y = o[i][1]*inv;
        st.z = o[i][2]*inv; st.w = o[i][3]*inv;
        *(float4*)&Obase[(size_t)(q0 + ty*4 + i)*DMODEL + tx*4] = st;
    }
}

// ---------------- launch ----------------
extern "C" void kernel_launch(void* const* d_in, const int* in_sizes, int n_in,
                              void* d_out, int out_size) {
    const float* x  = (const float*)d_in[0];
    const float* wq = (const float*)d_in[1];
    const float* bq = (const float*)d_in[2];
    const float* wk = (const float*)d_in[3];
    const float* bk = (const float*)d_in[4];
    const float* wv = (const float*)d_in[5];
    const float* bv = (const float*)d_in[6];
    const float* wo = (const float*)d_in[7];
    const float* bo = (const float*)d_in[8];
    float* out = (float*)d_out;

    float *Q, *K, *V, *A;
    cudaGetSymbolAddress((void**)&Q, g_Q);
    cudaGetSymbolAddress((void**)&K, g_K);
    cudaGetSymbolAddress((void**)&V, g_V);
    cudaGetSymbolAddress((void**)&A, g_attn);

    const int M = BB * SS;   // 4096

    // QKV projections
    gemm_tn<<<dim3(DMODEL/64, M/64), 256>>>(x, wq, bq, Q, M, DMODEL, DMODEL);
    gemm_tn<<<dim3(KVD/64,    M/64), 256>>>(x, wk, bk, K, M, KVD,    DMODEL);
    gemm_tn<<<dim3(KVD/64,    M/64), 256>>>(x, wv, bv, V, M, KVD,    DMODEL);

    // RoPE
    freq_kernel<<<(SS*(DK/2) + 255)/256, 256>>>();
    {
        int total = BB*SS*HQ*(DK/2) + BB*SS*HKV*(DK/2);
        rope_kernel<<<(total + 255)/256, 256>>>();
    }

    // attention
    attn_kernel<<<dim3(SS/64, BB*HQ), 256>>>();

    // output projection
    gemm_tn<<<dim3(DMODEL/64, M/64), 256>>>(A, wo, bo, out, M, DMODEL, DMODEL);
}

// round 2
// speedup vs baseline: 3.1734x; 3.1734x over previous
#include <cuda_runtime.h>
#include <math.h>
#include <stdint.h>

#define BB   2
#define SS   2048
#define DMODEL 1024
#define HQ   16
#define HKV  4
#define DK   64
#define KVD  256   // HKV*DK

// ---------------- scratch (no allocations allowed) ----------------
__device__ float g_Q[BB*SS*DMODEL];
__device__ float g_K[BB*SS*KVD];
__device__ float g_V[BB*SS*KVD];
__device__ float g_attn[BB*SS*DMODEL];

// ---------------- tf32 helpers ----------------
__device__ __forceinline__ uint32_t f2tf(float x) {
    uint32_t r; asm("cvt.rna.tf32.f32 %0, %1;" : "=r"(r) : "f"(x)); return r;
}

__device__ __forceinline__ void mma_tf32(float* c, const uint32_t* a, const uint32_t* b) {
    asm volatile(
        "mma.sync.aligned.m16n8k8.row.col.f32.tf32.tf32.f32 "
        "{%0,%1,%2,%3}, {%4,%5,%6,%7}, {%8,%9}, {%0,%1,%2,%3};\n"
        : "+f"(c[0]), "+f"(c[1]), "+f"(c[2]), "+f"(c[3])
        : "r"(a[0]), "r"(a[1]), "r"(a[2]), "r"(a[3]), "r"(b[0]), "r"(b[1]));
}

// ---------------- RoPE frequency quirk, fused into rope apply ----------------
// theta_j = 1/(10000^(2j)/64); j>=5 -> inf -> theta=0 (fp32 overflow, matches ref)
__global__ void freq_rope_kernel(float* __restrict__ cosT, float* __restrict__ sinT) {
    int idx = blockIdx.x * blockDim.x + threadIdx.x;
    if (idx >= SS * (DK/2)) return;
    int s = idx / (DK/2);
    int j = idx % (DK/2);
    float p = powf(10000.0f, 2.0f * (float)j);
    float theta = 1.0f / (p / (float)DK);
    float ang = (float)s * theta;
    double a = (double)ang;
    cosT[idx] = (float)cos(a);
    sinT[idx] = (float)sin(a);
}
__device__ float g_cos[SS*(DK/2)];
__device__ float g_sin[SS*(DK/2)];

// Reference quirk: out1 = x1*c - x2*s ; out2 = x2*s + x1*c
__global__ void rope_kernel() {
    int idx = blockIdx.x * blockDim.x + threadIdx.x;
    const int nQ = BB*SS*HQ*(DK/2);
    const int nK = BB*SS*HKV*(DK/2);
    if (idx < nQ) {
        int pr = idx & 31;
        int t  = idx >> 5;
        int h  = t % HQ;  t /= HQ;
        int s  = t % SS;
        int b  = t / SS;
        float* p = g_Q + ((size_t)(b*SS + s))*DMODEL + h*DK + pr*2;
        float c  = g_cos[s*(DK/2) + pr];
        float sn = g_sin[s*(DK/2) + pr];
        float x1 = p[0], x2 = p[1];
        p[0] = x1*c - x2*sn;
        p[1] = x2*sn + x1*c;
    } else if (idx < nQ + nK) {
        int j  = idx - nQ;
        int pr = j & 31;
        int t  = j >> 5;
        int h  = t % HKV; t /= HKV;
        int s  = t % SS;
        int b  = t / SS;
        float* p = g_K + ((size_t)(b*SS + s))*KVD + h*DK + pr*2;
        float c  = g_cos[s*(DK/2) + pr];
        float sn = g_sin[s*(DK/2) + pr];
        float x1 = p[0], x2 = p[1];
        p[0] = x1*c - x2*sn;
        p[1] = x2*sn + x1*c;
    }
}

// ---------------- tf32 tensor-core GEMM: C[M,N] = A[M,Kd]*W[N,Kd]^T + bias ----
// 128x128 block, kTile=16, 256 threads (8 warps, warp tile 64x32), double buffer.
#define GST 20   // smem row stride (20 % 32 == 20; fragment pattern verified CF)

__global__ void __launch_bounds__(256) gemm_tf32(
        const float* __restrict__ A, const float* __restrict__ W,
        const float* __restrict__ bias, float* __restrict__ C,
        int M, int N, int Kd) {
    __shared__ uint32_t As[2][128*GST];
    __shared__ uint32_t Bs[2][128*GST];
    int tid = threadIdx.x;
    int lane = tid & 31, warp = tid >> 5;
    int wm = warp >> 2, wn = warp & 3;          // 2 x 4 warp grid
    int rowbase = blockIdx.y*128, colbase = blockIdx.x*128;

    float acc[4][4][4];
#pragma unroll
    for (int a = 0; a < 4; a++)
#pragma unroll
        for (int b = 0; b < 4; b++)
#pragma unroll
            for (int c = 0; c < 4; c++) acc[a][b][c] = 0.0f;

    int lr = tid >> 2;          // 0..63
    int kc = (tid & 3) * 4;     // 0,4,8,12

    float4 pa[2], pw[2];
    // prefetch k-tile 0
#pragma unroll
    for (int i = 0; i < 2; i++) {
        pa[i] = *(const float4*)&A[(size_t)(rowbase + lr + 64*i)*Kd + 0 + kc];
        pw[i] = *(const float4*)&W[(size_t)(colbase + lr + 64*i)*Kd + 0 + kc];
    }
#pragma unroll
    for (int i = 0; i < 2; i++) {
        uint4 ua = {f2tf(pa[i].x), f2tf(pa[i].y), f2tf(pa[i].z), f2tf(pa[i].w)};
        *(uint4*)&As[0][(lr + 64*i)*GST + kc] = ua;
        uint4 uw = {f2tf(pw[i].x), f2tf(pw[i].y), f2tf(pw[i].z), f2tf(pw[i].w)};
        *(uint4*)&Bs[0][(lr + 64*i)*GST + kc] = uw;
    }
    __syncthreads();

    int nk = Kd / 16;
    for (int t = 0; t < nk; t++) {
        int s = t & 1;
        if (t + 1 < nk) {
            int kb = (t+1)*16;
#pragma unroll
            for (int i = 0; i < 2; i++) {
                pa[i] = *(const float4*)&A[(size_t)(rowbase + lr + 64*i)*Kd + kb + kc];
                pw[i] = *(const float4*)&W[(size_t)(colbase + lr + 64*i)*Kd + kb + kc];
            }
        }
        // compute on buffer s
#pragma unroll
        for (int ks = 0; ks < 2; ks++) {
            int k0 = ks * 8;
            uint32_t af[4][4], bf[4][2];
#pragma unroll
            for (int mi = 0; mi < 4; mi++) {
                int row = wm*64 + mi*16 + (lane >> 2);
                const uint32_t* p = &As[s][row*GST + k0 + (lane & 3)];
                af[mi][0] = p[0];
                af[mi][1] = p[8*GST];
                af[mi][2] = p[4];
                af[mi][3] = p[8*GST + 4];
            }
#pragma unroll
            for (int ni = 0; ni < 4; ni++) {
                int col = wn*32 + ni*8 + (lane >> 2);
                const uint32_t* p = &Bs[s][col*GST + k0 + (lane & 3)];
                bf[ni][0] = p[0];
                bf[ni][1] = p[4];
            }
#pragma unroll
            for (int mi = 0; mi < 4; mi++)
#pragma unroll
                for (int ni = 0; ni < 4; ni++)
                    mma_tf32(acc[mi][ni], af[mi], bf[ni]);
        }
        if (t + 1 < nk) {
            int sn = (t+1) & 1;
#pragma unroll
            for (int i = 0; i < 2; i++) {
                uint4 ua = {f2tf(pa[i].x), f2tf(pa[i].y), f2tf(pa[i].z), f2tf(pa[i].w)};
                *(uint4*)&As[sn][(lr + 64*i)*GST + kc] = ua;
                uint4 uw = {f2tf(pw[i].x), f2tf(pw[i].y), f2tf(pw[i].z), f2tf(pw[i].w)};
                *(uint4*)&Bs[sn][(lr + 64*i)*GST + kc] = uw;
            }
        }
        __syncthreads();
    }

    // epilogue
#pragma unroll
    for (int mi = 0; mi < 4; mi++) {
        int row = rowbase + wm*64 + mi*16 + (lane >> 2);
#pragma unroll
        for (int ni = 0; ni < 4; ni++) {
            int col = colbase + wn*32 + ni*8 + 2*(lane & 3);
            float b0 = bias[col], b1 = bias[col+1];
            float2 v0 = {acc[mi][ni][0] + b0, acc[mi][ni][1] + b1};
            *(float2*)&C[(size_t)row*N + col] = v0;
            float2 v1 = {acc[mi][ni][2] + b0, acc[mi][ni][3] + b1};
            *(float2*)&C[(size_t)(row+8)*N + col] = v1;
        }
    }
}

// ---------------- flash attention, tf32 tensor cores ----------------
// Block: 64 q-rows, 4 warps (16 rows each). Q frags live in regs whole block.
// Ks (stride 68) doubles as P^T buffer; Vs stride 72. Online softmax in
// C-fragment layout (row = 4-lane quad -> shfl.xor 1,2 reductions).
#define SKS 68
#define SVS 72

__global__ void __launch_bounds__(128) attn_tf32() {
    __shared__ uint32_t Ks[64*SKS];
    __shared__ uint32_t Vs[64*SVS];
    int tid = threadIdx.x, lane = tid & 31, warp = tid >> 5;
    int qt = (int)gridDim.x - 1 - (int)blockIdx.x;     // big tiles first
    int bh = blockIdx.y;
    int b = bh >> 4, h = bh & 15, kvh = h >> 2;
    const float* Qb = g_Q + (size_t)b*SS*DMODEL + h*DK;
    const float* Kb = g_K + (size_t)b*SS*KVD + kvh*DK;
    const float* Vb = g_V + (size_t)b*SS*KVD + kvh*DK;
    int q0 = qt * 64;
    int r1 = lane >> 2;              // 0..7
    int qrow = 16*warp + r1;         // local row (second row = +8)

    // Q fragments, pre-scaled by 1/sqrt(64)
    uint32_t qf[8][4];
#pragma unroll
    for (int kk = 0; kk < 8; kk++) {
        int d = kk*8 + (lane & 3);
        const float* p = &Qb[(size_t)(q0 + qrow)*DMODEL + d];
        qf[kk][0] = f2tf(p[0] * 0.125f);
        qf[kk][1] = f2tf(p[(size_t)8*DMODEL] * 0.125f);
        qf[kk][2] = f2tf(p[4] * 0.125f);
        qf[kk][3] = f2tf(p[(size_t)8*DMODEL + 4] * 0.125f);
    }

    float m1 = -1e30f, m2 = -1e30f, l1 = 0.0f, l2 = 0.0f;
    float of[8][4];
#pragma unroll
    for (int n = 0; n < 8; n++)
#pragma unroll
        for (int j = 0; j < 4; j++) of[n][j] = 0.0f;

    for (int kt = 0; kt <= qt; kt++) {
        int k0 = kt * 64;
        // load K,V tiles (tf32) — 8 float4 per thread per array
#pragma unroll
        for (int i = 0; i < 8; i++) {
            int j = tid + 128*i;
            int row = j >> 4, c = (j & 15) * 4;
            float4 kv = *(const float4*)&Kb[(size_t)(k0 + row)*KVD + c];
            uint4 uk = {f2tf(kv.x), f2tf(kv.y), f2tf(kv.z), f2tf(kv.w)};
            *(uint4*)&Ks[row*SKS + c] = uk;
            float4 vv = *(const float4*)&Vb[(size_t)(k0 + row)*KVD + c];
            uint4 uv = {f2tf(vv.x), f2tf(vv.y), f2tf(vv.z), f2tf(vv.w)};
            *(uint4*)&Vs[row*SVS + c] = uv;
        }
        __syncthreads();

        // S = (Q/8) K^T
        float sf[8][4];
#pragma unroll
        for (int n = 0; n < 8; n++)
#pragma unroll
            for (int j = 0; j < 4; j++) sf[n][j] = 0.0f;
#pragma unroll
        for (int n = 0; n < 8; n++) {
            int key = n*8 + r1;
#pragma unroll
            for (int kk = 0; kk < 8; kk++) {
                const uint32_t* p = &Ks[key*SKS + kk*8 + (lane & 3)];
                uint32_t bfr[2] = {p[0], p[4]};
                mma_tf32(sf[n], qf[kk], bfr);
            }
        }

        // causal mask on diagonal tile
        if (kt == qt) {
#pragma unroll
            for (int n = 0; n < 8; n++) {
                int col = n*8 + 2*(lane & 3);
                if (col     > qrow)     sf[n][0] = -1e30f;
                if (col + 1 > qrow)     sf[n][1] = -1e30f;
                if (col     > qrow + 8) sf[n][2] = -1e30f;
                if (col + 1 > qrow + 8) sf[n][3] = -1e30f;
            }
        }

        // online softmax (row quads: lanes differing in bits 0,1)
        float mx1 = -1e30f, mx2 = -1e30f;
#pragma unroll
        for (int n = 0; n < 8; n++) {
            mx1 = fmaxf(mx1, fmaxf(sf[n][0], sf[n][1]));
            mx2 = fmaxf(mx2, fmaxf(sf[n][2], sf[n][3]));
        }
        mx1 = fmaxf(mx1, __shfl_xor_sync(0xffffffffu, mx1, 1));
        mx1 = fmaxf(mx1, __shfl_xor_sync(0xffffffffu, mx1, 2));
        mx2 = fmaxf(mx2, __shfl_xor_sync(0xffffffffu, mx2, 1));
        mx2 = fmaxf(mx2, __shfl_xor_sync(0xffffffffu, mx2, 2));
        float mn1 = fmaxf(m1, mx1), mn2 = fmaxf(m2, mx2);
        float c1 = __expf(m1 - mn1), c2 = __expf(m2 - mn2);
        float s1 = 0.0f, s2 = 0.0f;
#pragma unroll
        for (int n = 0; n < 8; n++) {
            sf[n][0] = __expf(sf[n][0] - mn1);
            sf[n][1] = __expf(sf[n][1] - mn1);
            sf[n][2] = __expf(sf[n][2] - mn2);
            sf[n][3] = __expf(sf[n][3] - mn2);
            s1 += sf[n][0] + sf[n][1];
            s2 += sf[n][2] + sf[n][3];
        }
        s1 += __shfl_xor_sync(0xffffffffu, s1, 1);
        s1 += __shfl_xor_sync(0xffffffffu, s1, 2);
        s2 += __shfl_xor_sync(0xffffffffu, s2, 1);
        s2 += __shfl_xor_sync(0xffffffffu, s2, 2);
        l1 = l1*c1 + s1;  l2 = l2*c2 + s2;
        m1 = mn1;         m2 = mn2;
#pragma unroll
        for (int n = 0; n < 8; n++) {
            of[n][0] *= c1; of[n][1] *= c1;
            of[n][2] *= c2; of[n][3] *= c2;
        }

        __syncthreads();   // all warps done reading Ks as K
        // store P (tf32) into Ks; rows are warp-private
#pragma unroll
        for (int n = 0; n < 8; n++) {
            int col = n*8 + 2*(lane & 3);
            uint32_t p0 = f2tf(sf[n][0]), p1 = f2tf(sf[n][1]);
            *(uint2*)&Ks[qrow*SKS + col] = make_uint2(p0, p1);
            uint32_t p2 = f2tf(sf[n][2]), p3 = f2tf(sf[n][3]);
            *(uint2*)&Ks[(qrow+8)*SKS + col] = make_uint2(p2, p3);
        }
        __syncwarp();

        // O += P V
#pragma unroll
        for (int kk = 0; kk < 8; kk++) {
            const uint32_t* p = &Ks[qrow*SKS + kk*8 + (lane & 3)];
            uint32_t pa[4] = {p[0], p[8*SKS], p[4], p[8*SKS + 4]};
            int key = kk*8 + (lane & 3);
#pragma unroll
            for (int n = 0; n < 8; n++) {
                const uint32_t* pv = &Vs[key*SVS + n*8 + r1];
                uint32_t vb[2] = {pv[0], pv[4*SVS]};
                mma_tf32(of[n], pa, vb);
            }
        }
        __syncthreads();   // before next tile overwrites Ks/Vs
    }

    float inv1 = 1.0f / l1, inv2 = 1.0f / l2;
    float* Ob = g_attn + (size_t)b*SS*DMODEL + h*DK;
#pragma unroll
    for (int n = 0; n < 8; n++) {
        int col = n*8 + 2*(lane & 3);
        float2 v0 = {of[n][0]*inv1, of[n][1]*inv1};
        *(float2*)&Ob[(size_t)(q0 + qrow)*DMODEL + col] = v0;
        float2 v1 = {of[n][2]*inv2, of[n][3]*inv2};
        *(float2*)&Ob[(size_t)(q0 + qrow + 8)*DMODEL + col] = v1;
    }
}

// ---------------- launch ----------------
extern "C" void kernel_launch(void* const* d_in, const int* in_sizes, int n_in,
                              void* d_out, int out_size) {
    const float* x  = (const float*)d_in[0];
    const float* wq = (const float*)d_in[1];
    const float* bq = (const float*)d_in[2];
    const float* wk = (const float*)d_in[3];
    const float* bk = (const float*)d_in[4];
    const float* wv = (const float*)d_in[5];
    const float* bv = (const float*)d_in[6];
    const float* wo = (const float*)d_in[7];
    const float* bo = (const float*)d_in[8];
    float* out = (float*)d_out;

    float *Q, *K, *V, *A, *cT, *sT;
    cudaGetSymbolAddress((void**)&Q,  g_Q);
    cudaGetSymbolAddress((void**)&K,  g_K);
    cudaGetSymbolAddress((void**)&V,  g_V);
    cudaGetSymbolAddress((void**)&A,  g_attn);
    cudaGetSymbolAddress((void**)&cT, g_cos);
    cudaGetSymbolAddress((void**)&sT, g_sin);

    const int M = BB * SS;   // 4096

    // QKV projections (tf32 tensor cores)
    gemm_tf32<<<dim3(DMODEL/128, M/128), 256>>>(x, wq, bq, Q, M, DMODEL, DMODEL);
    gemm_tf32<<<dim3(KVD/128,    M/128), 256>>>(x, wk, bk, K, M, KVD,    DMODEL);
    gemm_tf32<<<dim3(KVD/128,    M/128), 256>>>(x, wv, bv, V, M, KVD,    DMODEL);

    // RoPE
    freq_rope_kernel<<<(SS*(DK/2) + 255)/256, 256>>>(cT, sT);
    {
        int total = BB*SS*HQ*(DK/2) + BB*SS*HKV*(DK/2);
        rope_kernel<<<(total + 255)/256, 256>>>();
    }

    // attention
    attn_tf32<<<dim3(SS/64, BB*HQ), 128>>>();

    // output projection
    gemm_tf32<<<dim3(DMODEL/128, M/128), 256>>>(A, wo, bo, out, M, DMODEL, DMODEL);
}

// round 4
// speedup vs baseline: 3.4851x; 1.0982x over previous
#include <cuda_runtime.h>
#include <math.h>
#include <stdint.h>

#define BB   2
#define SS   2048
#define DMODEL 1024
#define HQ   16
#define HKV  4
#define DK   64
#define KVD  256   // HKV*DK

// ---------------- scratch (no allocations allowed) ----------------
__device__ float g_Q[BB*SS*DMODEL];
__device__ float g_K[BB*SS*KVD];
__device__ float g_V[BB*SS*KVD];
__device__ float g_attn[BB*SS*DMODEL];
__device__ float g_cos[SS*(DK/2)];
__device__ float g_sin[SS*(DK/2)];

// ---------------- helpers ----------------
__device__ __forceinline__ uint32_t f2tf(float x) {
    uint32_t r; asm("cvt.rna.tf32.f32 %0, %1;" : "=r"(r) : "f"(x)); return r;
}

__device__ __forceinline__ void mma_tf32(float* c, const uint32_t* a, const uint32_t* b) {
    asm volatile(
        "mma.sync.aligned.m16n8k8.row.col.f32.tf32.tf32.f32 "
        "{%0,%1,%2,%3}, {%4,%5,%6,%7}, {%8,%9}, {%0,%1,%2,%3};\n"
        : "+f"(c[0]), "+f"(c[1]), "+f"(c[2]), "+f"(c[3])
        : "r"(a[0]), "r"(a[1]), "r"(a[2]), "r"(a[3]), "r"(b[0]), "r"(b[1]));
}

__device__ __forceinline__ uint32_t smem_u32(const void* p) {
    uint32_t a;
    asm("{ .reg .u64 t; cvta.to.shared.u64 t, %1; cvt.u32.u64 %0, t; }" : "=r"(a) : "l"(p));
    return a;
}

__device__ __forceinline__ void cp16(uint32_t saddr, const void* g) {
    asm volatile("cp.async.cg.shared.global [%0], [%1], 16;" :: "r"(saddr), "l"(g));
}
#define CP_COMMIT() asm volatile("cp.async.commit_group;" ::: "memory")
#define CP_WAIT0()  asm volatile("cp.async.wait_group 0;" ::: "memory")

// ---------------- RoPE table ----------------
// theta_j = 1/(10000^(2j)/64); j>=5 -> inf -> theta=0 (fp32 overflow, matches ref)
__global__ void freq_rope_kernel(float* __restrict__ cosT, float* __restrict__ sinT) {
    int idx = blockIdx.x * blockDim.x + threadIdx.x;
    if (idx >= SS * (DK/2)) return;
    int s = idx / (DK/2);
    int j = idx % (DK/2);
    float p = powf(10000.0f, 2.0f * (float)j);
    float theta = 1.0f / (p / (float)DK);
    float ang = (float)s * theta;
    double a = (double)ang;
    cosT[idx] = (float)cos(a);
    sinT[idx] = (float)sin(a);
}

// Reference quirk: out1 = x1*c - x2*s ; out2 = x2*s + x1*c
__global__ void rope_kernel() {
    int idx = blockIdx.x * blockDim.x + threadIdx.x;
    const int nQ = BB*SS*HQ*(DK/2);
    const int nK = BB*SS*HKV*(DK/2);
    if (idx < nQ) {
        int pr = idx & 31;
        int t  = idx >> 5;
        int h  = t % HQ;  t /= HQ;
        int s  = t % SS;
        int b  = t / SS;
        float* p = g_Q + ((size_t)(b*SS + s))*DMODEL + h*DK + pr*2;
        float c  = g_cos[s*(DK/2) + pr];
        float sn = g_sin[s*(DK/2) + pr];
        float x1 = p[0], x2 = p[1];
        p[0] = x1*c - x2*sn;
        p[1] = x2*sn + x1*c;
    } else if (idx < nQ + nK) {
        int j  = idx - nQ;
        int pr = j & 31;
        int t  = j >> 5;
        int h  = t % HKV; t /= HKV;
        int s  = t % SS;
        int b  = t / SS;
        float* p = g_K + ((size_t)(b*SS + s))*KVD + h*DK + pr*2;
        float c  = g_cos[s*(DK/2) + pr];
        float sn = g_sin[s*(DK/2) + pr];
        float x1 = p[0], x2 = p[1];
        p[0] = x1*c - x2*sn;
        p[1] = x2*sn + x1*c;
    }
}

// ---------------- tf32 tensor-core GEMM (R2-identical numerics) ---------------
// C[M,N] = A[M,Kd]*W[N,Kd]^T + bias. blockIdx.z selects (W0,b0,C0)/(W1,b1,C1).
#define GST 20

__global__ void __launch_bounds__(256) gemm_tf32(
        const float* __restrict__ A,
        const float* __restrict__ W0, const float* __restrict__ b0v, float* __restrict__ C0,
        const float* __restrict__ W1, const float* __restrict__ b1v, float* __restrict__ C1,
        int N, int Kd) {
    __shared__ uint32_t As[2][128*GST];
    __shared__ uint32_t Bs[2][128*GST];
    const float* W    = blockIdx.z ? W1 : W0;
    const float* bias = blockIdx.z ? b1v : b0v;
    float*       C    = blockIdx.z ? C1 : C0;
    int tid = threadIdx.x;
    int lane = tid & 31, warp = tid >> 5;
    int wm = warp >> 2, wn = warp & 3;
    int rowbase = blockIdx.y*128, colbase = blockIdx.x*128;

    float acc[4][4][4];
#pragma unroll
    for (int a = 0; a < 4; a++)
#pragma unroll
        for (int b = 0; b < 4; b++)
#pragma unroll
            for (int c = 0; c < 4; c++) acc[a][b][c] = 0.0f;

    int lr = tid >> 2;
    int kc = (tid & 3) * 4;

    float4 pa[2], pw[2];
#pragma unroll
    for (int i = 0; i < 2; i++) {
        pa[i] = *(const float4*)&A[(size_t)(rowbase + lr + 64*i)*Kd + 0 + kc];
        pw[i] = *(const float4*)&W[(size_t)(colbase + lr + 64*i)*Kd + 0 + kc];
    }
#pragma unroll
    for (int i = 0; i < 2; i++) {
        uint4 ua = {f2tf(pa[i].x), f2tf(pa[i].y), f2tf(pa[i].z), f2tf(pa[i].w)};
        *(uint4*)&As[0][(lr + 64*i)*GST + kc] = ua;
        uint4 uw = {f2tf(pw[i].x), f2tf(pw[i].y), f2tf(pw[i].z), f2tf(pw[i].w)};
        *(uint4*)&Bs[0][(lr + 64*i)*GST + kc] = uw;
    }
    __syncthreads();

    int nk = Kd / 16;
    for (int t = 0; t < nk; t++) {
        int s = t & 1;
        if (t + 1 < nk) {
            int kb = (t+1)*16;
#pragma unroll
            for (int i = 0; i < 2; i++) {
                pa[i] = *(const float4*)&A[(size_t)(rowbase + lr + 64*i)*Kd + kb + kc];
                pw[i] = *(const float4*)&W[(size_t)(colbase + lr + 64*i)*Kd + kb + kc];
            }
        }
#pragma unroll
        for (int ks = 0; ks < 2; ks++) {
            int k0 = ks * 8;
            uint32_t af[4][4], bf[4][2];
#pragma unroll
            for (int mi = 0; mi < 4; mi++) {
                int row = wm*64 + mi*16 + (lane >> 2);
                const uint32_t* p = &As[s][row*GST + k0 + (lane & 3)];
                af[mi][0] = p[0];
                af[mi][1] = p[8*GST];
                af[mi][2] = p[4];
                af[mi][3] = p[8*GST + 4];
            }
#pragma unroll
            for (int ni = 0; ni < 4; ni++) {
                int col = wn*32 + ni*8 + (lane >> 2);
                const uint32_t* p = &Bs[s][col*GST + k0 + (lane & 3)];
                bf[ni][0] = p[0];
                bf[ni][1] = p[4];
            }
#pragma unroll
            for (int mi = 0; mi < 4; mi++)
#pragma unroll
                for (int ni = 0; ni < 4; ni++)
                    mma_tf32(acc[mi][ni], af[mi], bf[ni]);
        }
        if (t + 1 < nk) {
            int sn = (t+1) & 1;
#pragma unroll
            for (int i = 0; i < 2; i++) {
                uint4 ua = {f2tf(pa[i].x), f2tf(pa[i].y), f2tf(pa[i].z), f2tf(pa[i].w)};
                *(uint4*)&As[sn][(lr + 64*i)*GST + kc] = ua;
                uint4 uw = {f2tf(pw[i].x), f2tf(pw[i].y), f2tf(pw[i].z), f2tf(pw[i].w)};
                *(uint4*)&Bs[sn][(lr + 64*i)*GST + kc] = uw;
            }
        }
        __syncthreads();
    }

#pragma unroll
    for (int mi = 0; mi < 4; mi++) {
        int row = rowbase + wm*64 + mi*16 + (lane >> 2);
#pragma unroll
        for (int ni = 0; ni < 4; ni++) {
            int col = colbase + wn*32 + ni*8 + 2*(lane & 3);
            float c0 = bias[col], c1 = bias[col+1];
            float2 v0 = {acc[mi][ni][0] + c0, acc[mi][ni][1] + c1};
            *(float2*)&C[(size_t)row*N + col] = v0;
            float2 v1 = {acc[mi][ni][2] + c0, acc[mi][ni][3] + c1};
            *(float2*)&C[(size_t)(row+8)*N + col] = v1;
        }
    }
}

// ---------------- flash attention, tf32 mma.sync, GQA-fused --------------------
// CTA: 256 threads = 8 warps = 2 q-heads x 4 row-subtiles; 64 q-rows; shared K/V.
// Double-buffered tf32 K/V stages + single raw fp32 cp.async stage.
// Numerically bit-identical to the R2 kernel (same cvt points, same MMA order).
#define SKS 68
#define SVS 72
#define STAGE_W (64*SKS + 64*SVS)          // 8960 words per tf32 stage
#define ATT_SMEM (2*STAGE_W*4 + 8192*4)    // 104448 bytes

__global__ void __launch_bounds__(256, 2) attn_tf32() {
    extern __shared__ uint32_t smA[];
    uint32_t* TF  = smA;                       // 2 tf32 stages
    float*    RAW = (float*)(smA + 2*STAGE_W); // K raw [0,4096), V raw [4096,8192)
    uint32_t rawK = smem_u32(RAW);
    uint32_t rawV = rawK + 4096*4;

    int tid = threadIdx.x, lane = tid & 31, warp = tid >> 5;
    int g = warp >> 2, sub = warp & 3;
    int qt = (int)gridDim.x - 1 - (int)blockIdx.x;
    int y = blockIdx.y;                        // 16: (b, kvh, head-pair)
    int b = y >> 3, kvh = (y >> 1) & 3, hg = y & 1;
    int h = kvh*4 + hg*2 + g;

    const float* Qb = g_Q + (size_t)b*SS*DMODEL + h*DK;
    const float* Kb = g_K + (size_t)b*SS*KVD + kvh*DK;
    const float* Vb = g_V + (size_t)b*SS*KVD + kvh*DK;
    int q0 = qt * 64;
    int r1 = lane >> 2;
    int qrow = 16*sub + r1;

    // Q fragments, pre-scaled by 1/sqrt(64)
    uint32_t qf[8][4];
#pragma unroll
    for (int kk = 0; kk < 8; kk++) {
        int d = kk*8 + (lane & 3);
        const float* p = &Qb[(size_t)(q0 + qrow)*DMODEL + d];
        qf[kk][0] = f2tf(p[0] * 0.125f);
        qf[kk][1] = f2tf(p[(size_t)8*DMODEL] * 0.125f);
        qf[kk][2] = f2tf(p[4] * 0.125f);
        qf[kk][3] = f2tf(p[(size_t)8*DMODEL + 4] * 0.125f);
    }

    float m1 = -1e30f, m2 = -1e30f, l1 = 0.0f, l2 = 0.0f;
    float of[8][4];
#pragma unroll
    for (int n = 0; n < 8; n++)
#pragma unroll
        for (int j = 0; j < 4; j++) of[n][j] = 0.0f;

    // shuffle-transpose lane math
    int q = lane & 3;
    int srcA = (lane & ~3) | (q >> 1);
    int srcB = srcA + 2;
    int qodd = q & 1;

    // prefetch tile 0 into RAW
#pragma unroll
    for (int i = 0; i < 4; i++) {
        int idx = tid + 256*i;
        int row = idx >> 4, c4 = idx & 15;
        cp16(rawK + idx*16, &Kb[(size_t)(0 + row)*KVD + c4*4]);
        cp16(rawV + idx*16, &Vb[(size_t)(0 + row)*KVD + c4*4]);
    }
    CP_COMMIT();
    CP_WAIT0();
    // cvt into stage 0 (same-thread bytes)
#pragma unroll
    for (int i = 0; i < 4; i++) {
        int idx = tid + 256*i;
        int row = idx >> 4, c4 = idx & 15;
        float4 kv = *(const float4*)&RAW[idx*4];
        uint4 uk = {f2tf(kv.x), f2tf(kv.y), f2tf(kv.z), f2tf(kv.w)};
        *(uint4*)&TF[row*SKS + c4*4] = uk;
        float4 vv = *(const float4*)&RAW[4096 + idx*4];
        uint4 uv = {f2tf(vv.x), f2tf(vv.y), f2tf(vv.z), f2tf(vv.w)};
        *(uint4*)&TF[64*SKS + row*SVS + c4*4] = uv;
    }
    __syncthreads();

    for (int kt = 0; kt <= qt; kt++) {
        int s = kt & 1;
        const uint32_t* Ks = TF + s*STAGE_W;
        const uint32_t* Vs = Ks + 64*SKS;

        // issue cp.async for next tile
        if (kt < qt) {
            int k0n = (kt+1)*64;
#pragma unroll
            for (int i = 0; i < 4; i++) {
                int idx = tid + 256*i;
                int row = idx >> 4, c4 = idx & 15;
                cp16(rawK + idx*16, &Kb[(size_t)(k0n + row)*KVD + c4*4]);
                cp16(rawV + idx*16, &Vb[(size_t)(k0n + row)*KVD + c4*4]);
            }
            CP_COMMIT();
        }

        // S = (Q/8) K^T
        float sf[8][4];
#pragma unroll
        for (int n = 0; n < 8; n++)
#pragma unroll
            for (int j = 0; j < 4; j++) sf[n][j] = 0.0f;
#pragma unroll
        for (int n = 0; n < 8; n++) {
            int key = n*8 + r1;
#pragma unroll
            for (int kk = 0; kk < 8; kk++) {
                const uint32_t* p = &Ks[key*SKS + kk*8 + (lane & 3)];
                uint32_t bfr[2] = {p[0], p[4]};
                mma_tf32(sf[n], qf[kk], bfr);
            }
        }

        // causal mask on diagonal tile
        if (kt == qt) {
#pragma unroll
            for (int n = 0; n < 8; n++) {
                int col = n*8 + 2*(lane & 3);
                if (col     > qrow)     sf[n][0] = -1e30f;
                if (col + 1 > qrow)     sf[n][1] = -1e30f;
                if (col     > qrow + 8) sf[n][2] = -1e30f;
                if (col + 1 > qrow + 8) sf[n][3] = -1e30f;
            }
        }

        // online softmax
        float mx1 = -1e30f, mx2 = -1e30f;
#pragma unroll
        for (int n = 0; n < 8; n++) {
            mx1 = fmaxf(mx1, fmaxf(sf[n][0], sf[n][1]));
            mx2 = fmaxf(mx2, fmaxf(sf[n][2], sf[n][3]));
        }
        mx1 = fmaxf(mx1, __shfl_xor_sync(0xffffffffu, mx1, 1));
        mx1 = fmaxf(mx1, __shfl_xor_sync(0xffffffffu, mx1, 2));
        mx2 = fmaxf(mx2, __shfl_xor_sync(0xffffffffu, mx2, 1));
        mx2 = fmaxf(mx2, __shfl_xor_sync(0xffffffffu, mx2, 2));
        float mn1 = fmaxf(m1, mx1), mn2 = fmaxf(m2, mx2);
        float c1 = __expf(m1 - mn1), c2 = __expf(m2 - mn2);
        float s1 = 0.0f, s2 = 0.0f;
#pragma unroll
        for (int n = 0; n < 8; n++) {
            sf[n][0] = __expf(sf[n][0] - mn1);
            sf[n][1] = __expf(sf[n][1] - mn1);
            sf[n][2] = __expf(sf[n][2] - mn2);
            sf[n][3] = __expf(sf[n][3] - mn2);
            s1 += sf[n][0] + sf[n][1];
            s2 += sf[n][2] + sf[n][3];
        }
        s1 += __shfl_xor_sync(0xffffffffu, s1, 1);
        s1 += __shfl_xor_sync(0xffffffffu, s1, 2);
        s2 += __shfl_xor_sync(0xffffffffu, s2, 1);
        s2 += __shfl_xor_sync(0xffffffffu, s2, 2);
        l1 = l1*c1 + s1;  l2 = l2*c2 + s2;
        m1 = mn1;         m2 = mn2;
#pragma unroll
        for (int n = 0; n < 8; n++) {
            of[n][0] *= c1; of[n][1] *= c1;
            of[n][2] *= c2; of[n][3] *= c2;
        }

        // P -> tf32 (same rounding point as R2's smem store)
        uint32_t pt[8][4];
#pragma unroll
        for (int n = 0; n < 8; n++) {
            pt[n][0] = f2tf(sf[n][0]);
            pt[n][1] = f2tf(sf[n][1]);
            pt[n][2] = f2tf(sf[n][2]);
            pt[n][3] = f2tf(sf[n][3]);
        }

        // O += P V ; A-fragment of P built by in-quad shuffles (no smem)
#pragma unroll
        for (int kk = 0; kk < 8; kk++) {
            uint32_t v00 = __shfl_sync(0xffffffffu, pt[kk][0], srcA);
            uint32_t v01 = __shfl_sync(0xffffffffu, pt[kk][1], srcA);
            uint32_t v10 = __shfl_sync(0xffffffffu, pt[kk][2], srcA);
            uint32_t v11 = __shfl_sync(0xffffffffu, pt[kk][3], srcA);
            uint32_t v20 = __shfl_sync(0xffffffffu, pt[kk][0], srcB);
            uint32_t v21 = __shfl_sync(0xffffffffu, pt[kk][1], srcB);
            uint32_t v30 = __shfl_sync(0xffffffffu, pt[kk][2], srcB);
            uint32_t v31 = __shfl_sync(0xffffffffu, pt[kk][3], srcB);
            uint32_t pa[4];
            pa[0] = qodd ? v01 : v00;   // P[r1  ][kk*8+q]
            pa[1] = qodd ? v11 : v10;   // P[r1+8][kk*8+q]
            pa[2] = qodd ? v21 : v20;   // P[r1  ][kk*8+q+4]
            pa[3] = qodd ? v31 : v30;   // P[r1+8][kk*8+q+4]
            int key = kk*8 + (lane & 3);
#pragma unroll
            for (int n = 0; n < 8; n++) {
                const uint32_t* pv = &Vs[key*SVS + n*8 + r1];
                uint32_t vb[2] = {pv[0], pv[4*SVS]};
                mma_tf32(of[n], pa, vb);
            }
        }

        // land next tile: wait cp.async, cvt into the other stage
        if (kt < qt) {
            CP_WAIT0();
            uint32_t* KsN = TF + (s^1)*STAGE_W;
            uint32_t* VsN = KsN + 64*SKS;
#pragma unroll
            for (int i = 0; i < 4; i++) {
                int idx = tid + 256*i;
                int row = idx >> 4, c4 = idx & 15;
                float4 kv = *(const float4*)&RAW[idx*4];
                uint4 uk = {f2tf(kv.x), f2tf(kv.y), f2tf(kv.z), f2tf(kv.w)};
                *(uint4*)&KsN[row*SKS + c4*4] = uk;
                float4 vv = *(const float4*)&RAW[4096 + idx*4];
                uint4 uv = {f2tf(vv.x), f2tf(vv.y), f2tf(vv.z), f2tf(vv.w)};
                *(uint4*)&VsN[row*SVS + c4*4] = uv;
            }
        }
        __syncthreads();
    }

    float inv1 = 1.0f / l1, inv2 = 1.0f / l2;
    float* Ob = g_attn + (size_t)b*SS*DMODEL + h*DK;
#pragma unroll
    for (int n = 0; n < 8; n++) {
        int col = n*8 + 2*(lane & 3);
        float2 v0 = {of[n][0]*inv1, of[n][1]*inv1};
        *(float2*)&Ob[(size_t)(q0 + qrow)*DMODEL + col] = v0;
        float2 v1 = {of[n][2]*inv2, of[n][3]*inv2};
        *(float2*)&Ob[(size_t)(q0 + qrow + 8)*DMODEL + col] = v1;
    }
}

// ---------------- launch ----------------
extern "C" void kernel_launch(void* const* d_in, const int* in_sizes, int n_in,
                              void* d_out, int out_size) {
    const float* x  = (const float*)d_in[0];
    const float* wq = (const float*)d_in[1];
    const float* bq = (const float*)d_in[2];
    const float* wk = (const float*)d_in[3];
    const float* bk = (const float*)d_in[4];
    const float* wv = (const float*)d_in[5];
    const float* bv = (const float*)d_in[6];
    const float* wo = (const float*)d_in[7];
    const float* bo = (const float*)d_in[8];
    float* out = (float*)d_out;

    float *Q, *K, *V, *A, *cT, *sT;
    cudaGetSymbolAddress((void**)&Q,  g_Q);
    cudaGetSymbolAddress((void**)&K,  g_K);
    cudaGetSymbolAddress((void**)&V,  g_V);
    cudaGetSymbolAddress((void**)&A,  g_attn);
    cudaGetSymbolAddress((void**)&cT, g_cos);
    cudaGetSymbolAddress((void**)&sT, g_sin);

    static int cfg_done = 0;
    if (!cfg_done) {
        cudaFuncSetAttribute(attn_tf32, cudaFuncAttributeMaxDynamicSharedMemorySize, ATT_SMEM);
        cfg_done = 1;
    }

    const int M = BB * SS;   // 4096

    // Q projection
    gemm_tf32<<<dim3(DMODEL/128, M/128, 1), 256>>>(
        x, wq, bq, Q, wq, bq, Q, DMODEL, DMODEL);
    // K + V projections fused on blockIdx.z
    gemm_tf32<<<dim3(KVD/128, M/128, 2), 256>>>(
        x, wk, bk, K, wv, bv, V, KVD, DMODEL);

    // RoPE
    freq_rope_kernel<<<(SS*(DK/2) + 255)/256, 256>>>(cT, sT);
    {
        int total = BB*SS*HQ*(DK/2) + BB*SS*HKV*(DK/2);
        rope_kernel<<<(total + 255)/256, 256>>>();
    }

    // attention (2 heads per CTA share K/V)
    attn_tf32<<<dim3(SS/64, BB*HKV*2), 256, ATT_SMEM>>>();

    // output projection
    gemm_tf32<<<dim3(DMODEL/128, M/128, 1), 256>>>(
        A, wo, bo, out, wo, bo, out, DMODEL, DMODEL);
}